// round 2
// baseline (speedup 1.0000x reference)
#include <cuda_runtime.h>
#include <math.h>

#define NPTS 64     // NUM_POINTS
#define NCF  32     // NUM_COEFF
#define NB   30     // NUM_COEFF - 2
#define NITER 20
#define NPROB (256*512)
#define PI_D 3.14159265358979323846

// ------------------------ device scratch (double, setup only) ---------------
__device__ double scr_T[NCF][NPTS];
__device__ double scr_DT[NCF][NPTS];
__device__ double scr_Gb[NB][NPTS];
__device__ double scr_M[NB][2*NB];
__device__ double scr_Cd[NPTS][NB];
__device__ double scr_tch[NPTS];
__device__ double scr_Dt[NPTS];
__device__ double scr_P0[NB], scr_P1[NB];

// ------------------------ constants for the main kernel (float) -------------
__device__ float c_G[NPTS][NCF];    // G[k][m] = T[m+2](tch_k) - P0[m] - P1[m]*tch_k ; pad m=30,31 -> 0
__device__ float c_C[NPTS][NCF];    // C[k][m] ; pad -> 0
__device__ float c_V[NCF];          // v[m] = sum_k C[k][m]
__device__ float c_P0[NCF], c_P1[NCF];
__device__ float c_tc1[NPTS];       // 1 + tch[k]
__device__ float c_sin[NPTS];       // sin(t_true[k])
__device__ float c_PO[NCF][16];     // Phi_out[c][t]
__device__ float c_scal[2];         // inv_s = (t1-t0)/2 , sin(t0)

// ==================== setup kernel: 1 block, 256 threads, fp64 ==============
__global__ void setup_kernel(const float* __restrict__ tspan) {
    int tid = threadIdx.x;
    double t0 = (double)tspan[0];
    double t1 = (double)tspan[15];
    double inv_s = 0.5 * (t1 - t0);
    __shared__ int s_piv;
    __shared__ double s_fac[NB];

    // --- Chebyshev points, T grid (T0..T31), DT grid (n*U_{n-1}) ---
    if (tid < NPTS) {
        scr_tch[tid] = -cos(PI_D * (double)tid / (double)NPTS);
    }
    __syncthreads();
    if (tid < NPTS) {
        double tnext = (tid == NPTS-1) ? 1.0 : scr_tch[tid+1];
        scr_Dt[tid]  = tnext - scr_tch[tid];
        double t = scr_tch[tid];
        double Tm2 = 1.0, Tm1 = t;
        scr_T[0][tid] = 1.0; scr_T[1][tid] = t;
        #pragma unroll 1
        for (int n = 2; n < NCF; n++) {
            double Tn = 2.0*t*Tm1 - Tm2; scr_T[n][tid] = Tn; Tm2 = Tm1; Tm1 = Tn;
        }
        double Ua = 1.0, Ub = 2.0*t;           // U0, U1
        scr_DT[0][tid] = 0.0;
        scr_DT[1][tid] = 1.0;                  // 1*U0
        scr_DT[2][tid] = 2.0*Ub;               // 2*U1
        #pragma unroll 1
        for (int n = 3; n < NCF; n++) {        // DT[n] = n*U_{n-1}
            double Uc = 2.0*t*Ub - Ua;
            scr_DT[n][tid] = (double)n * Uc;
            Ua = Ub; Ub = Uc;
        }
    }
    __syncthreads();

    // --- P = Phi_tail @ inv0 (s-independent) ---
    if (tid < NB) {
        double d0 = scr_DT[tid+2][0];
        scr_P1[tid] = d0;
        scr_P0[tid] = scr_T[tid+2][0] + d0;
    }
    __syncthreads();

    // --- Gb[m][k] = DT[m+2][k] - P1[m] ---
    for (int e = tid; e < NB*NPTS; e += blockDim.x) {
        int m = e / NPTS, k = e % NPTS;
        scr_Gb[m][k] = scr_DT[m+2][k] - scr_P1[m];
    }
    __syncthreads();

    // --- A = Gb * diag(Dt) * Gb^T ; build [A | I] ---
    for (int e = tid; e < NB*NB; e += blockDim.x) {
        int i = e / NB, j = e % NB;
        double s = 0.0;
        for (int k = 0; k < NPTS; k++) s += scr_Gb[i][k]*scr_Dt[k]*scr_Gb[j][k];
        scr_M[i][j] = s;
        scr_M[i][NB+j] = (i == j) ? 1.0 : 0.0;
    }
    __syncthreads();

    // --- Gauss-Jordan inverse with partial pivoting (fp64) ---
    for (int col = 0; col < NB; col++) {
        if (tid == 0) {
            int p = col; double best = fabs(scr_M[col][col]);
            for (int r = col+1; r < NB; r++) {
                double v = fabs(scr_M[r][col]);
                if (v > best) { best = v; p = r; }
            }
            s_piv = p;
        }
        __syncthreads();
        int p = s_piv;
        if (p != col && tid < 2*NB) {
            double tmp = scr_M[col][tid]; scr_M[col][tid] = scr_M[p][tid]; scr_M[p][tid] = tmp;
        }
        __syncthreads();
        double piv = scr_M[col][col];
        __syncthreads();
        if (tid < 2*NB) scr_M[col][tid] = scr_M[col][tid] / piv;
        if (tid < NB)   s_fac[tid] = scr_M[tid][col];   // read before elimination (col entry unused for r==col)
        __syncthreads();
        for (int e = tid; e < NB*2*NB; e += blockDim.x) {
            int r = e / (2*NB), c = e % (2*NB);
            if (r != col) scr_M[r][c] -= s_fac[r] * scr_M[col][c];
        }
        __syncthreads();
    }

    // --- C[k][m] = Dt[k] * sum_j Gb[j][k] * Q[j][m] ---
    for (int e = tid; e < NPTS*NB; e += blockDim.x) {
        int k = e / NB, m = e % NB;
        double s = 0.0;
        for (int j = 0; j < NB; j++) s += scr_Gb[j][k] * scr_M[j][NB+m];
        scr_Cd[k][m] = scr_Dt[k] * s;
    }
    __syncthreads();

    // --- float constant tables ---
    for (int e = tid; e < NPTS*NCF; e += blockDim.x) {
        int k = e / NCF, m = e % NCF;
        float g = 0.f, cc = 0.f;
        if (m < NB) {
            g  = (float)(scr_T[m+2][k] - scr_P0[m] - scr_P1[m]*scr_tch[k]);
            cc = (float)scr_Cd[k][m];
        }
        c_G[k][m] = g;
        c_C[k][m] = cc;
    }
    if (tid < NCF) {
        double v = 0.0, p0 = 0.0, p1 = 0.0;
        if (tid < NB) {
            for (int k = 0; k < NPTS; k++) v += scr_Cd[k][tid];
            p0 = scr_P0[tid]; p1 = scr_P1[tid];
        }
        c_V[tid] = (float)v; c_P0[tid] = (float)p0; c_P1[tid] = (float)p1;
    }
    if (tid < NPTS) {
        c_tc1[tid] = (float)(1.0 + scr_tch[tid]);
        c_sin[tid] = (float)sin(t0 + inv_s * (scr_tch[tid] + 1.0));
    }
    if (tid == 0) { c_scal[0] = (float)inv_s; c_scal[1] = (float)sin(t0); }
    if (tid < 16) {
        double tq = -1.0 + 2.0*((double)tspan[tid] - t0)/(t1 - t0);
        double Tm2 = 1.0, Tm1 = tq;
        c_PO[0][tid] = 1.0f; c_PO[1][tid] = (float)tq;
        #pragma unroll 1
        for (int n = 2; n < NCF; n++) {
            double Tn = 2.0*tq*Tm1 - Tm2; c_PO[n][tid] = (float)Tn; Tm2 = Tm1; Tm1 = Tn;
        }
    }
}

// ==================== main solve kernel =====================================
__device__ __forceinline__ float fast_tanh(float x) {
    float ax = fabsf(x);
    float e  = __expf(-2.0f * ax);                 // MUFU.EX2 path, ~2 ulp
    float t  = __fdividef(1.0f - e, 1.0f + e);     // MUFU.RCP path
    return copysignf(t, x);
}

__global__ void __launch_bounds__(128, 3) solve_kernel(
    const float* __restrict__ y_init, const float* __restrict__ Bin,
    const float* __restrict__ a, float* __restrict__ out)
{
    __shared__ float sG[NPTS][NCF];
    __shared__ float sC[NPTS][NCF];
    __shared__ float sTc1[NPTS], sSin[NPTS];
    __shared__ float sV[NCF], sP0[NCF], sP1[NCF];
    __shared__ float sPO[NCF][16];
    __shared__ float sScal[2];

    int tid = threadIdx.x;
    for (int e = tid; e < NPTS*NCF; e += 128) {
        (&sG[0][0])[e] = (&c_G[0][0])[e];
        (&sC[0][0])[e] = (&c_C[0][0])[e];
    }
    if (tid < NPTS) { sTc1[tid] = c_tc1[tid]; sSin[tid] = c_sin[tid]; }
    if (tid < NCF)  { sV[tid] = c_V[tid]; sP0[tid] = c_P0[tid]; sP1[tid] = c_P1[tid]; }
    for (int e = tid; e < NCF*16; e += 128) (&sPO[0][0])[e] = (&c_PO[0][0])[e];
    if (tid < 2) sScal[tid] = c_scal[tid];
    __syncthreads();

    int idx  = blockIdx.x * 128 + tid;
    float y  = y_init[idx];
    float aj = a[idx & 511];
    float invs = sScal[0];
    float f0 = sScal[1] - fast_tanh(y * aj);
    float w  = f0 * invs;            // f0 / s

    float B[NCF];
    #pragma unroll
    for (int m = 0; m < NB; m++) B[m] = Bin[idx*NB + m];
    B[30] = 0.f; B[31] = 0.f;

    #pragma unroll 1
    for (int it = 0; it < NITER; it++) {
        float acc[NCF];
        #pragma unroll
        for (int m = 0; m < NCF; m++) acc[m] = 0.f;
        #pragma unroll 4
        for (int k = 0; k < NPTS; k++) {
            float ya = fmaf(w, sTc1[k], y);
            const float4* g4 = (const float4*)&sG[k][0];
            #pragma unroll
            for (int q = 0; q < 8; q++) {
                float4 g = g4[q];
                ya = fmaf(B[4*q+0], g.x, ya);
                ya = fmaf(B[4*q+1], g.y, ya);
                ya = fmaf(B[4*q+2], g.z, ya);
                ya = fmaf(B[4*q+3], g.w, ya);
            }
            float f = sSin[k] - fast_tanh(ya * aj);
            const float4* c4 = (const float4*)&sC[k][0];
            #pragma unroll
            for (int q = 0; q < 8; q++) {
                float4 c = c4[q];
                acc[4*q+0] = fmaf(f, c.x, acc[4*q+0]);
                acc[4*q+1] = fmaf(f, c.y, acc[4*q+1]);
                acc[4*q+2] = fmaf(f, c.z, acc[4*q+2]);
                acc[4*q+3] = fmaf(f, c.w, acc[4*q+3]);
            }
        }
        #pragma unroll
        for (int m = 0; m < NB; m++) B[m] = fmaf(invs, acc[m], -(w * sV[m]));
    }

    // head = yf@inv0 - B@P
    float h0 = y + w, h1 = w;
    #pragma unroll
    for (int m = 0; m < NB; m++) {
        h0 = fmaf(-B[m], sP0[m], h0);
        h1 = fmaf(-B[m], sP1[m], h1);
    }

    // B_full: (256,512,32) after the approx block
    float* outB = out + 16*NPROB;
    int b = idx * NCF;
    outB[b]   = h0;
    outB[b+1] = h1;
    #pragma unroll
    for (int m = 0; m < NB; m++) outB[b+2+m] = B[m];

    // approx: (16,256,512), coalesced over idx
    #pragma unroll
    for (int t = 0; t < 16; t++) {
        float val = fmaf(h0, sPO[0][t], h1 * sPO[1][t]);
        #pragma unroll
        for (int m = 0; m < NB; m++) val = fmaf(B[m], sPO[m+2][t], val);
        out[t*NPROB + idx] = val;
    }
}

// ==================== launch ================================================
extern "C" void kernel_launch(void* const* d_in, const int* in_sizes, int n_in,
                              void* d_out, int out_size) {
    const float* y_init = (const float*)d_in[0];
    const float* B_init = (const float*)d_in[1];
    const float* t_span = (const float*)d_in[2];
    const float* a      = (const float*)d_in[3];
    float* out = (float*)d_out;
    setup_kernel<<<1, 256>>>(t_span);
    solve_kernel<<<NPROB/128, 128>>>(y_init, B_init, a, out);
}